// round 9
// baseline (speedup 1.0000x reference)
#include <cuda_runtime.h>

// RMSNorm over last axis: x[32768 rows, 2048] fp32, weight[2048] fp32.
// R7 variant: 512 threads/CTA, EXACTLY 1 float4 per thread (MLP_p1=1) to
// minimize cross-CTA L1tex-queue contention / multi-CTA spread (B300 model:
// spr_max floor 1.10 @ MLP_p1=1 vs ~1.17+ @ MLP_p1=2).
// Single pass: load (streaming) -> reduce sum(x^2) -> rsqrt -> scale -> store.
// Exact-once HBM traffic: 256 MiB read + 256 MiB write; weight L2-resident.

#define ROW_LEN 2048
#define THREADS 512
#define NWARPS  (THREADS / 32)   // 16

__global__ __launch_bounds__(THREADS)
void rmsnorm_kernel(const float* __restrict__ x,
                    const float* __restrict__ w,
                    float* __restrict__ out)
{
    const size_t row = blockIdx.x;
    const float4* __restrict__ xr = reinterpret_cast<const float4*>(x + row * ROW_LEN);
    float4* __restrict__ outr     = reinterpret_cast<float4*>(out + row * ROW_LEN);
    const float4* __restrict__ w4 = reinterpret_cast<const float4*>(w);

    const int t = threadIdx.x;

    // Exactly ONE streaming 128-bit load per thread (MLP_p1 = 1).
    float4 v = __ldcs(&xr[t]);

    // Weight load issued early (8 KB, L2-resident) to overlap the reduction.
    float4 wv = __ldg(&w4[t]);

    // Per-thread sum of squares.
    float ss = v.x * v.x + v.y * v.y + v.z * v.z + v.w * v.w;

    // Warp reduce.
    #pragma unroll
    for (int off = 16; off > 0; off >>= 1)
        ss += __shfl_xor_sync(0xFFFFFFFFu, ss, off);

    // Cross-warp reduce: one barrier, then every thread sums the 16 warp
    // partials itself (broadcast LDS, conflict-free) and computes rsqrt.
    __shared__ float warp_sums[NWARPS];
    const int lane = t & 31;
    const int wid  = t >> 5;
    if (lane == 0) warp_sums[wid] = ss;
    __syncthreads();

    float s = 0.0f;
    #pragma unroll
    for (int i = 0; i < NWARPS; i++)
        s += warp_sums[i];

    const float inv = rsqrtf(s * (1.0f / (float)ROW_LEN) + 1e-6f);

    float4 o;
    o.x = v.x * inv * wv.x;
    o.y = v.y * inv * wv.y;
    o.z = v.z * inv * wv.z;
    o.w = v.w * inv * wv.w;

    // Streaming store (evict-first: output not re-read).
    __stcs(&outr[t], o);
}

extern "C" void kernel_launch(void* const* d_in, const int* in_sizes, int n_in,
                              void* d_out, int out_size)
{
    const float* x = (const float*)d_in[0];
    const float* w = (const float*)d_in[1];
    float* out     = (float*)d_out;

    const int rows = out_size / ROW_LEN;  // 32768
    rmsnorm_kernel<<<rows, THREADS>>>(x, w, out);
}

// round 12
// speedup vs baseline: 1.1795x; 1.1795x over previous
#include <cuda_runtime.h>

// RMSNorm over last axis: x[32768 rows, 2048] fp32, weight[2048] fp32.
// R9 variant: 2 rows per CTA, 256 threads, 4 front-batched LDG.128 per thread
// (MLP_p1=4). Measured: DRAM% is monotone-increasing in per-warp MLP
// (MLP=1 -> 61.7%, MLP=2 -> 80.2%); this pushes in-flight loads/SM to ~128
// to fully cover the ~577cyc DRAM latency.
// Single pass, exact-once traffic, one barrier, dual accumulators.

#define ROW_LEN 2048
#define THREADS 256
#define NWARPS  (THREADS / 32)   // 8
#define V4_ROW  (ROW_LEN / 4)    // 512 float4 per row

__global__ __launch_bounds__(THREADS)
void rmsnorm_kernel(const float* __restrict__ x,
                    const float* __restrict__ w,
                    float* __restrict__ out)
{
    const size_t row0 = (size_t)blockIdx.x * 2;
    const float4* __restrict__ xr0 = reinterpret_cast<const float4*>(x + row0 * ROW_LEN);
    const float4* __restrict__ xr1 = xr0 + V4_ROW;
    float4* __restrict__ or0       = reinterpret_cast<float4*>(out + row0 * ROW_LEN);
    float4* __restrict__ or1       = or0 + V4_ROW;
    const float4* __restrict__ w4  = reinterpret_cast<const float4*>(w);

    const int t = threadIdx.x;

    // Four front-batched 128-bit streaming loads (MLP_p1 = 4).
    float4 a0 = __ldcs(&xr0[t]);
    float4 a1 = __ldcs(&xr0[t + THREADS]);
    float4 b0 = __ldcs(&xr1[t]);
    float4 b1 = __ldcs(&xr1[t + THREADS]);

    // Weight loads (8 KB, L2-resident) issued early to overlap the reduction.
    float4 w0 = __ldg(&w4[t]);
    float4 w1 = __ldg(&w4[t + THREADS]);

    // Per-thread sum of squares, one accumulator per row.
    float s0 = a0.x * a0.x + a0.y * a0.y + a0.z * a0.z + a0.w * a0.w
             + a1.x * a1.x + a1.y * a1.y + a1.z * a1.z + a1.w * a1.w;
    float s1 = b0.x * b0.x + b0.y * b0.y + b0.z * b0.z + b0.w * b0.w
             + b1.x * b1.x + b1.y * b1.y + b1.z * b1.z + b1.w * b1.w;

    // Warp reduce both accumulators (interleaved).
    #pragma unroll
    for (int off = 16; off > 0; off >>= 1) {
        s0 += __shfl_xor_sync(0xFFFFFFFFu, s0, off);
        s1 += __shfl_xor_sync(0xFFFFFFFFu, s1, off);
    }

    // Cross-warp reduce: one barrier, every thread sums the 8 partials per row.
    __shared__ float sums0[NWARPS];
    __shared__ float sums1[NWARPS];
    const int lane = t & 31;
    const int wid  = t >> 5;
    if (lane == 0) { sums0[wid] = s0; sums1[wid] = s1; }
    __syncthreads();

    float t0 = 0.0f, t1 = 0.0f;
    #pragma unroll
    for (int i = 0; i < NWARPS; i++) { t0 += sums0[i]; t1 += sums1[i]; }

    const float inv0 = rsqrtf(t0 * (1.0f / (float)ROW_LEN) + 1e-6f);
    const float inv1 = rsqrtf(t1 * (1.0f / (float)ROW_LEN) + 1e-6f);

    float4 o;
    o.x = a0.x * inv0 * w0.x;  o.y = a0.y * inv0 * w0.y;
    o.z = a0.z * inv0 * w0.z;  o.w = a0.w * inv0 * w0.w;
    __stcs(&or0[t], o);
    o.x = a1.x * inv0 * w1.x;  o.y = a1.y * inv0 * w1.y;
    o.z = a1.z * inv0 * w1.z;  o.w = a1.w * inv0 * w1.w;
    __stcs(&or0[t + THREADS], o);
    o.x = b0.x * inv1 * w0.x;  o.y = b0.y * inv1 * w0.y;
    o.z = b0.z * inv1 * w0.z;  o.w = b0.w * inv1 * w0.w;
    __stcs(&or1[t], o);
    o.x = b1.x * inv1 * w1.x;  o.y = b1.y * inv1 * w1.y;
    o.z = b1.z * inv1 * w1.z;  o.w = b1.w * inv1 * w1.w;
    __stcs(&or1[t + THREADS], o);
}

extern "C" void kernel_launch(void* const* d_in, const int* in_sizes, int n_in,
                              void* d_out, int out_size)
{
    const float* x = (const float*)d_in[0];
    const float* w = (const float*)d_in[1];
    float* out     = (float*)d_out;

    const int rows = out_size / ROW_LEN;  // 32768
    rmsnorm_kernel<<<rows / 2, THREADS>>>(x, w, out);
}